// round 3
// baseline (speedup 1.0000x reference)
#include <cuda_runtime.h>
#include <math.h>

#define HIDDEN 64
#define MBATCH 32
#define ATOM   64
#define NUM_RBF 300

#define S_INT   512
#define TAB_ROWS 515                    // row s holds h((s-1)*H_STEP)
#define H_STEP  (10.0f / 512.0f)
#define INV_H   51.2f

typedef unsigned long long u64;

// device scratch (no allocations allowed)
__device__ __align__(16) float g_table[TAB_ROWS * HIDDEN];
__device__ __align__(16) float g_v1[MBATCH * ATOM * HIDDEN];
__device__ __align__(16) float g_W2t[HIDDEN * HIDDEN];
__device__ __align__(16) float g_W3t[HIDDEN * HIDDEN];

__device__ __forceinline__ float softplus_f(float v) {
    return fmaxf(v, 0.0f) + log1pf(expf(-fabsf(v)));
}

// packed f32x2 helpers (Blackwell FFMA2)
__device__ __forceinline__ u64 fma2(u64 a, u64 b, u64 c) {
    u64 d; asm("fma.rn.f32x2 %0, %1, %2, %3;" : "=l"(d) : "l"(a), "l"(b), "l"(c)); return d;
}
__device__ __forceinline__ u64 mul2(u64 a, u64 b) {
    u64 d; asm("mul.rn.f32x2 %0, %1, %2;" : "=l"(d) : "l"(a), "l"(b)); return d;
}
__device__ __forceinline__ u64 dup2(float v) {
    u64 d; asm("mov.b64 %0, {%1, %1};" : "=l"(d) : "f"(v)); return d;
}

// ---------------------------------------------------------------------------
// Prep kernel, 512 threads/block:
//   blocks [0,33):   h(d) table, 16 samples per block
//   blocks [33,97):  v1 = x@W1^T + b1, block=(m, i-half)
//   block 97:        transpose W2, W3
// ---------------------------------------------------------------------------
#define TAB_BLOCKS 33
#define V1_BLOCKS  64
#define PREP_BLOCKS (TAB_BLOCKS + V1_BLOCKS + 1)
#define PREP_SMEM ((64*301 + 64*65 + 16*304 + 16*64) * 4)

__global__ void __launch_bounds__(512) prep_kernel(
    const float* __restrict__ x,  const float* __restrict__ W1, const float* __restrict__ b1,
    const float* __restrict__ W2, const float* __restrict__ W3,
    const float* __restrict__ Wd1, const float* __restrict__ bd1,
    const float* __restrict__ Wd2, const float* __restrict__ bd2)
{
    extern __shared__ float sh[];
    const int tid = threadIdx.x;
    const int b = blockIdx.x;

    if (b < TAB_BLOCKS) {
        float* Wd1_s = sh;                   // 64 x 301 (padded)
        float* Wd2_s = Wd1_s + 64 * 301;     // 64 x 65
        float* rbf_s = Wd2_s + 64 * 65;      // 16 x 304
        float* g_s   = rbf_s + 16 * 304;     // 16 x 64

        for (int idx = tid; idx < 64 * NUM_RBF; idx += 512) {
            int cc = idx / NUM_RBF;
            int r  = idx - cc * NUM_RBF;
            Wd1_s[cc * 301 + r] = Wd1[idx];
        }
        for (int idx = tid; idx < 4096; idx += 512)
            Wd2_s[(idx >> 6) * 65 + (idx & 63)] = Wd2[idx];
        const int s0 = b * 16;
        for (int idx = tid; idx < 16 * NUM_RBF; idx += 512) {
            int qq = idx / NUM_RBF;
            int r  = idx - qq * NUM_RBF;
            float dd = (float)(s0 + qq - 1) * H_STEP;
            float u = dd - 0.1f * (float)r;
            rbf_s[qq * 304 + r] = __expf(-10.0f * u * u);
        }
        __syncthreads();

        const int c = tid & 63;
        const float* wrow = Wd1_s + c * 301;
        #pragma unroll
        for (int q2 = 0; q2 < 2; q2++) {
            const int q = (tid >> 6) + q2 * 8;
            const float d = (float)(s0 + q - 1) * H_STEP;
            int rlo = (int)ceilf((d - 1.5f) * 10.0f); if (rlo < 0) rlo = 0;
            int rhi = (int)floorf((d + 1.5f) * 10.0f); if (rhi > NUM_RBF - 1) rhi = NUM_RBF - 1;
            float p = bd1[c];
            const float* rrow = rbf_s + q * 304;
            for (int r = rlo; r <= rhi; r++) p = fmaf(wrow[r], rrow[r], p);
            g_s[q * 64 + c] = softplus_f(p);
        }
        __syncthreads();
        const float* w2row = Wd2_s + c * 65;
        #pragma unroll
        for (int q2 = 0; q2 < 2; q2++) {
            const int q = (tid >> 6) + q2 * 8;
            const int s = s0 + q;
            float qv = bd2[c];
            const float* gg = g_s + q * 64;
            #pragma unroll 8
            for (int k = 0; k < 64; k++) qv = fmaf(w2row[k], gg[k], qv);
            if (s < TAB_ROWS) g_table[s * 64 + c] = softplus_f(qv);
        }
    } else if (b < TAB_BLOCKS + V1_BLOCKS) {
        const int v = b - TAB_BLOCKS;
        const int m = v >> 1, half = v & 1;
        float* W1p = sh;                 // 64 x 68 padded
        float* xp  = sh + 64 * 68;       // 32 x 68

        for (int idx = tid; idx < 4096; idx += 512)
            W1p[(idx >> 6) * 68 + (idx & 63)] = W1[idx];
        for (int idx = tid; idx < 2048; idx += 512)
            xp[(idx >> 6) * 68 + (idx & 63)] = x[m * 4096 + (half * 32 + (idx >> 6)) * 64 + (idx & 63)];
        __syncthreads();

        const int ii = tid & 31;
        const int oh = tid >> 5;
        float4 acc = make_float4(0.f, 0.f, 0.f, 0.f);
        const float* xr = xp + ii * 68;
        const float* wr = W1p + oh * 4 * 68;
        #pragma unroll
        for (int c4 = 0; c4 < 16; c4++) {
            float4 xv = *(const float4*)(xr + c4 * 4);
            float4 w0 = *(const float4*)(wr + 0 * 68 + c4 * 4);
            float4 w1 = *(const float4*)(wr + 1 * 68 + c4 * 4);
            float4 w2 = *(const float4*)(wr + 2 * 68 + c4 * 4);
            float4 w3 = *(const float4*)(wr + 3 * 68 + c4 * 4);
            acc.x = fmaf(xv.x, w0.x, fmaf(xv.y, w0.y, fmaf(xv.z, w0.z, fmaf(xv.w, w0.w, acc.x))));
            acc.y = fmaf(xv.x, w1.x, fmaf(xv.y, w1.y, fmaf(xv.z, w1.z, fmaf(xv.w, w1.w, acc.y))));
            acc.z = fmaf(xv.x, w2.x, fmaf(xv.y, w2.y, fmaf(xv.z, w2.z, fmaf(xv.w, w2.w, acc.z))));
            acc.w = fmaf(xv.x, w3.x, fmaf(xv.y, w3.y, fmaf(xv.z, w3.z, fmaf(xv.w, w3.w, acc.w))));
        }
        float4 bv = *(const float4*)(b1 + oh * 4);
        acc.x += bv.x; acc.y += bv.y; acc.z += bv.z; acc.w += bv.w;
        *(float4*)(g_v1 + (m * 64 + half * 32 + ii) * 64 + oh * 4) = acc;
    } else {
        for (int idx = tid; idx < 8192; idx += 512) {
            const float* src = (idx < 4096) ? W2 : W3;
            float* dst = (idx < 4096) ? g_W2t : g_W3t;
            int e = idx & 4095;
            dst[e] = src[(e & 63) * 64 + (e >> 6)];
        }
    }
}

// ---------------------------------------------------------------------------
// Main kernel: 128 blocks = (m, j-group of 16), 512 threads (16 warps),
// 128-reg budget. thread = (ihalf, jj, cidx), 32 i-iters each, f32x2 FMA.
// ---------------------------------------------------------------------------
#define MAIN_SMEM ((32960 + 4096 + 4096 + 1024 + 2048 + 1024 + 1024 + 64 + 64) * 4)  // 185600 B

__global__ void __launch_bounds__(512) main_kernel(
    const float* __restrict__ x, const float* __restrict__ dist,
    const float* __restrict__ b2, const float* __restrict__ b3,
    float* __restrict__ out)
{
    extern __shared__ float sh[];
    float* TAB  = sh;                    // 32960 (reused for W2T/W3T in epilogue)
    float* V1s  = TAB + 32960;           // 4096
    float* W4s  = V1s + 4096;            // 4096 : per-pair cubic weights (float4)
    int*   KKs  = (int*)(W4s + 4096);    // 1024 : per-pair table byte offset k*256
    float* PART = (float*)(KKs + 1024);  // 2048 : 2-way partials
    float* PAIR = PART + 2048;           // 1024
    float* V2s  = PAIR + 1024;           // 1024
    float* B2s  = V2s + 1024;            // 64
    float* B3s  = B2s + 64;              // 64

    const int tid = threadIdx.x;
    const int m  = blockIdx.x >> 2;
    const int j0 = (blockIdx.x & 3) << 4;

    // stage table + v1 + biases
    {
        const float4* ts = (const float4*)g_table;
        float4* td = (float4*)TAB;
        #pragma unroll
        for (int r = 0; r < 16; r++) td[tid + r * 512] = ts[tid + r * 512];
        if (tid < 48) td[8192 + tid] = ts[8192 + tid];
        const float4* vs = (const float4*)(g_v1 + m * 4096);
        float4* vd = (float4*)V1s;
        vd[tid] = vs[tid];
        vd[tid + 512] = vs[tid + 512];
        if (tid < 64) B2s[tid] = b2[tid];
        else if (tid < 128) B3s[tid - 64] = b3[tid - 64];
    }
    // per-pair cubic Lagrange weights (nodes -1,0,1,2)
    #pragma unroll
    for (int p = tid; p < 1024; p += 512) {
        const int i = p >> 4, jj = p & 15;
        float d = dist[(m * 64 + i) * 64 + j0 + jj];
        float t = d * INV_H;
        int k = (int)t;
        k = min(max(k, 0), S_INT - 1);
        float u = t - (float)k;
        float um1 = u - 1.0f, um2 = u - 2.0f, up1 = u + 1.0f;
        float4 w;
        w.x = -u * um1 * um2 * (1.0f / 6.0f);
        w.y =  up1 * um1 * um2 * 0.5f;
        w.z = -up1 * u * um2 * 0.5f;
        w.w =  up1 * u * um1 * (1.0f / 6.0f);
        ((float4*)W4s)[p] = w;
        KKs[p] = k << 8;                 // byte offset of first tap row
    }
    __syncthreads();

    const int ihalf = tid >> 8;          // 0..1
    const int jj    = (tid >> 4) & 15;   // destination atom within group
    const int cidx  = tid & 15;          // float4 channel group

    u64 acc0 = 0ull, acc1 = 0ull;
    const char* tb = (const char*)TAB + (cidx << 4);
    const ulonglong2* V1v = (const ulonglong2*)V1s;
    const float4* W4v = (const float4*)W4s;
    const int ibase = ihalf << 5;

    int p = (ibase << 4) + jj;
    #pragma unroll 4
    for (int ii = 0; ii < 32; ii++, p += 16) {
        float4 w = W4v[p];
        int koff = KKs[p];
        const char* a = tb + koff;
        ulonglong2 t0 = *(const ulonglong2*)(a);
        ulonglong2 t1 = *(const ulonglong2*)(a + 256);
        ulonglong2 t2 = *(const ulonglong2*)(a + 512);
        ulonglong2 t3 = *(const ulonglong2*)(a + 768);
        ulonglong2 vv = V1v[((ibase + ii) << 4) + cidx];
        u64 wx = dup2(w.x), wy = dup2(w.y), wz = dup2(w.z), ww = dup2(w.w);
        u64 h0 = fma2(wx, t0.x, fma2(wy, t1.x, fma2(wz, t2.x, mul2(ww, t3.x))));
        u64 h1 = fma2(wx, t0.y, fma2(wy, t1.y, fma2(wz, t2.y, mul2(ww, t3.y))));
        acc0 = fma2(vv.x, h0, acc0);
        acc1 = fma2(vv.y, h1, acc1);
    }
    {
        ulonglong2 r; r.x = acc0; r.y = acc1;
        ((ulonglong2*)PART)[(ihalf << 8) + (jj << 4) + cidx] = r;
    }
    __syncthreads();

    // reduce 2-way partials; stage W2T/W3T into dead TAB region
    if (tid < 256) {
        float4 a0 = ((const float4*)PART)[tid];
        float4 a1 = ((const float4*)PART)[256 + tid];
        float4 s4;
        s4.x = a0.x + a1.x; s4.y = a0.y + a1.y;
        s4.z = a0.z + a1.z; s4.w = a0.w + a1.w;
        ((float4*)PAIR)[tid] = s4;
    }
    float* W2Ts = TAB;
    float* W3Ts = TAB + 4096;
    {
        const float4* w2s = (const float4*)g_W2t;
        const float4* w3s = (const float4*)g_W3t;
        ((float4*)W2Ts)[tid]       = w2s[tid];
        ((float4*)W2Ts)[tid + 512] = w2s[tid + 512];
        ((float4*)W3Ts)[tid]       = w3s[tid];
        ((float4*)W3Ts)[tid + 512] = w3s[tid + 512];
    }
    __syncthreads();

    const int jj2 = tid >> 5;   // 0..15
    const int o   = tid & 31;   // handles o and o+32

    // layer 2: v2 = softplus(PAIR @ W2^T + b2)
    {
        float a0 = B2s[o], a1 = B2s[o + 32];
        const float* pr = PAIR + jj2 * 64;
        #pragma unroll 8
        for (int c = 0; c < 64; c++) {
            float pv = pr[c];
            a0 = fmaf(pv, W2Ts[c * 64 + o], a0);
            a1 = fmaf(pv, W2Ts[c * 64 + o + 32], a1);
        }
        V2s[jj2 * 64 + o]      = softplus_f(a0);
        V2s[jj2 * 64 + o + 32] = softplus_f(a1);
    }
    __syncthreads();

    // layer 3 + residual
    {
        float a0 = B3s[o], a1 = B3s[o + 32];
        const float* pr = V2s + jj2 * 64;
        #pragma unroll 8
        for (int c = 0; c < 64; c++) {
            float pv = pr[c];
            a0 = fmaf(pv, W3Ts[c * 64 + o], a0);
            a1 = fmaf(pv, W3Ts[c * 64 + o + 32], a1);
        }
        const int gidx = (m * 64 + j0 + jj2) * 64 + o;
        out[gidx]      = x[gidx] + a0;
        out[gidx + 32] = x[gidx + 32] + a1;
    }
}

extern "C" void kernel_launch(void* const* d_in, const int* in_sizes, int n_in,
                              void* d_out, int out_size) {
    const float* x   = (const float*)d_in[0];
    const float* dist= (const float*)d_in[1];
    const float* W1  = (const float*)d_in[2];
    const float* b1  = (const float*)d_in[3];
    const float* W2  = (const float*)d_in[4];
    const float* b2  = (const float*)d_in[5];
    const float* W3  = (const float*)d_in[6];
    const float* b3  = (const float*)d_in[7];
    const float* Wd1 = (const float*)d_in[8];
    const float* bd1 = (const float*)d_in[9];
    const float* Wd2 = (const float*)d_in[10];
    const float* bd2 = (const float*)d_in[11];
    float* out = (float*)d_out;
    (void)in_sizes; (void)n_in; (void)out_size;

    cudaFuncSetAttribute(prep_kernel, cudaFuncAttributeMaxDynamicSharedMemorySize, PREP_SMEM);
    cudaFuncSetAttribute(main_kernel, cudaFuncAttributeMaxDynamicSharedMemorySize, MAIN_SMEM);

    prep_kernel<<<PREP_BLOCKS, 512, PREP_SMEM>>>(x, W1, b1, W2, W3, Wd1, bd1, Wd2, bd2);
    main_kernel<<<128, 512, MAIN_SMEM>>>(x, dist, b2, b3, out);
}

// round 4
// speedup vs baseline: 1.1936x; 1.1936x over previous
#include <cuda_runtime.h>
#include <cuda_fp16.h>
#include <math.h>

#define HIDDEN 64
#define MBATCH 32
#define ATOM   64
#define NUM_RBF 300

#define S_INT   512
#define TAB_ROWS 513                    // row s = h(s*H_STEP), s in [0,512]
#define H_STEP  (10.0f / 512.0f)
#define INV_H   51.2f

typedef unsigned long long u64;

// device scratch (no allocations allowed). __device__ globals are zero-init.
__device__ __align__(16) unsigned g_table_h[515 * 32];   // fp16x2 table, row=128B
__device__ __align__(16) float g_v1[MBATCH * ATOM * HIDDEN];
__device__ __align__(16) float g_W2t[HIDDEN * HIDDEN];
__device__ __align__(16) float g_W3t[HIDDEN * HIDDEN];

__device__ __forceinline__ float softplus_f(float v) {
    return fmaxf(v, 0.0f) + log1pf(expf(-fabsf(v)));
}

// packed f32x2 helpers (Blackwell FFMA2)
__device__ __forceinline__ u64 fma2(u64 a, u64 b, u64 c) {
    u64 d; asm("fma.rn.f32x2 %0, %1, %2, %3;" : "=l"(d) : "l"(a), "l"(b), "l"(c)); return d;
}
__device__ __forceinline__ u64 pack2(float a, float b) {
    u64 d; asm("mov.b64 %0, {%1, %2};" : "=l"(d) : "f"(a), "f"(b)); return d;
}
__device__ __forceinline__ float2 unpk2(u64 v) {
    float2 f; asm("mov.b64 {%0, %1}, %2;" : "=f"(f.x), "=f"(f.y) : "l"(v)); return f;
}
__device__ __forceinline__ u64 dup2(float v) {
    u64 d; asm("mov.b64 %0, {%1, %1};" : "=l"(d) : "f"(v)); return d;
}
__device__ __forceinline__ unsigned h2bits(float w) {
    __half2 h = __float2half2_rn(w);
    return *reinterpret_cast<unsigned*>(&h);
}
__device__ __forceinline__ __half2 bits2h(unsigned u) {
    return *reinterpret_cast<__half2*>(&u);
}

// ---------------------------------------------------------------------------
// Prep kernel, 512 threads/block:
//   blocks [0,65):    h(d) table (fp16), 8 samples/block, one (s,c) per thread
//   blocks [65,129):  v1 = x@W1^T + b1
//   block 129:        transpose W2, W3
// ---------------------------------------------------------------------------
#define TAB_BLOCKS 65
#define V1_BLOCKS  64
#define PREP_BLOCKS (TAB_BLOCKS + V1_BLOCKS + 1)
#define PREP_SMEM ((64*301 + 64*65 + 8*304 + 8*64) * 4)

__global__ void __launch_bounds__(512) prep_kernel(
    const float* __restrict__ x,  const float* __restrict__ W1, const float* __restrict__ b1,
    const float* __restrict__ W2, const float* __restrict__ W3,
    const float* __restrict__ Wd1, const float* __restrict__ bd1,
    const float* __restrict__ Wd2, const float* __restrict__ bd2)
{
    extern __shared__ float sh[];
    const int tid = threadIdx.x;
    const int b = blockIdx.x;

    if (b < TAB_BLOCKS) {
        float* Wd1_s = sh;                   // 64 x 301 (padded)
        float* Wd2_s = Wd1_s + 64 * 301;     // 64 x 65
        float* rbf_s = Wd2_s + 64 * 65;      // 8 x 304
        float* g_s   = rbf_s + 8 * 304;      // 8 x 64

        for (int idx = tid; idx < 64 * NUM_RBF; idx += 512) {
            int cc = idx / NUM_RBF;
            int r  = idx - cc * NUM_RBF;
            Wd1_s[cc * 301 + r] = Wd1[idx];
        }
        for (int idx = tid; idx < 4096; idx += 512)
            Wd2_s[(idx >> 6) * 65 + (idx & 63)] = Wd2[idx];
        const int s0 = b * 8;
        for (int idx = tid; idx < 8 * NUM_RBF; idx += 512) {
            int qq = idx / NUM_RBF;
            int r  = idx - qq * NUM_RBF;
            float dd = (float)(s0 + qq) * H_STEP;
            float u = dd - 0.1f * (float)r;
            rbf_s[qq * 304 + r] = __expf(-10.0f * u * u);
        }
        __syncthreads();

        const int q = tid >> 6;
        const int c = tid & 63;
        const int s = s0 + q;
        const float d = (float)s * H_STEP;
        // only RBFs within |d - 0.1r| <= 1.5 contribute (> 1.7e-10)
        int rlo = (int)ceilf((d - 1.5f) * 10.0f); if (rlo < 0) rlo = 0;
        int rhi = (int)floorf((d + 1.5f) * 10.0f); if (rhi > NUM_RBF - 1) rhi = NUM_RBF - 1;
        float p = bd1[c];
        const float* wrow = Wd1_s + c * 301;
        const float* rrow = rbf_s + q * 304;
        for (int r = rlo; r <= rhi; r++) p = fmaf(wrow[r], rrow[r], p);
        g_s[q * 64 + c] = softplus_f(p);
        __syncthreads();

        float qv = bd2[c];
        const float* w2row = Wd2_s + c * 65;
        const float* gg = g_s + q * 64;
        #pragma unroll 8
        for (int k = 0; k < 64; k++) qv = fmaf(w2row[k], gg[k], qv);
        if (s < TAB_ROWS)
            ((__half*)g_table_h)[s * 64 + c] = __float2half_rn(softplus_f(qv));
    } else if (b < TAB_BLOCKS + V1_BLOCKS) {
        const int v = b - TAB_BLOCKS;
        const int m = v >> 1, half = v & 1;
        float* W1p = sh;                 // 64 x 68 padded
        float* xp  = sh + 64 * 68;       // 32 x 68

        for (int idx = tid; idx < 4096; idx += 512)
            W1p[(idx >> 6) * 68 + (idx & 63)] = W1[idx];
        for (int idx = tid; idx < 2048; idx += 512)
            xp[(idx >> 6) * 68 + (idx & 63)] = x[m * 4096 + (half * 32 + (idx >> 6)) * 64 + (idx & 63)];
        __syncthreads();

        const int ii = tid & 31;
        const int oh = tid >> 5;
        float4 acc = make_float4(0.f, 0.f, 0.f, 0.f);
        const float* xr = xp + ii * 68;
        const float* wr = W1p + oh * 4 * 68;
        #pragma unroll
        for (int c4 = 0; c4 < 16; c4++) {
            float4 xv = *(const float4*)(xr + c4 * 4);
            float4 w0 = *(const float4*)(wr + 0 * 68 + c4 * 4);
            float4 w1 = *(const float4*)(wr + 1 * 68 + c4 * 4);
            float4 w2 = *(const float4*)(wr + 2 * 68 + c4 * 4);
            float4 w3 = *(const float4*)(wr + 3 * 68 + c4 * 4);
            acc.x = fmaf(xv.x, w0.x, fmaf(xv.y, w0.y, fmaf(xv.z, w0.z, fmaf(xv.w, w0.w, acc.x))));
            acc.y = fmaf(xv.x, w1.x, fmaf(xv.y, w1.y, fmaf(xv.z, w1.z, fmaf(xv.w, w1.w, acc.y))));
            acc.z = fmaf(xv.x, w2.x, fmaf(xv.y, w2.y, fmaf(xv.z, w2.z, fmaf(xv.w, w2.w, acc.z))));
            acc.w = fmaf(xv.x, w3.x, fmaf(xv.y, w3.y, fmaf(xv.z, w3.z, fmaf(xv.w, w3.w, acc.w))));
        }
        float4 bv = *(const float4*)(b1 + oh * 4);
        acc.x += bv.x; acc.y += bv.y; acc.z += bv.z; acc.w += bv.w;
        *(float4*)(g_v1 + (m * 64 + half * 32 + ii) * 64 + oh * 4) = acc;
    } else {
        for (int idx = tid; idx < 8192; idx += 512) {
            const float* src = (idx < 4096) ? W2 : W3;
            float* dst = (idx < 4096) ? g_W2t : g_W3t;
            int e = idx & 4095;
            dst[e] = src[(e & 63) * 64 + (e >> 6)];
        }
    }
}

// ---------------------------------------------------------------------------
// Main kernel: 128 blocks = (m, j-group of 16), 512 threads (16 warps).
// Warp = destination atom jj; lane = channel pair (2t, 2t+1). Quadratic
// 3-tap interpolation of the fp16 table — all smem accesses conflict-free.
// ---------------------------------------------------------------------------
// shared carve (in 4B units): TAB 16480 | V1 4096 | W4 4096 | PAIR 1024 |
// V2 1024 | B2 64 | B3 64   = 26848 units = 107392 B.
// Request 120KB so only one CTA per SM (full crossbar per CTA).
#define MAIN_SMEM 122880

__global__ void __launch_bounds__(512) main_kernel(
    const float* __restrict__ x, const float* __restrict__ dist,
    const float* __restrict__ b2, const float* __restrict__ b3,
    float* __restrict__ out)
{
    extern __shared__ float sh[];
    unsigned* TABu = (unsigned*)sh;       // 16480 u32 (fp16 table; reused W2T/W3T)
    float* V1s  = sh + 16480;             // 4096
    float* W4s  = V1s + 4096;             // 4096 : per-pair (wm,w0,wp as h2 bits, koff)
    float* PAIRs= W4s + 4096;             // 1024
    float* V2s  = PAIRs + 1024;           // 1024
    float* B2s  = V2s + 1024;             // 64
    float* B3s  = B2s + 64;               // 64

    const int tid = threadIdx.x;
    const int m  = blockIdx.x >> 2;
    const int j0 = (blockIdx.x & 3) << 4;

    // stage table (fp16, 64.4KB) + v1 + biases
    {
        const uint4* ts = (const uint4*)g_table_h;
        uint4* td = (uint4*)TABu;
        for (int idx = tid; idx < 4120; idx += 512) td[idx] = ts[idx];
        const float4* vs = (const float4*)(g_v1 + m * 4096);
        float4* vd = (float4*)V1s;
        vd[tid] = vs[tid];
        vd[tid + 512] = vs[tid + 512];
        if (tid < 64) B2s[tid] = b2[tid];
        else if (tid < 128) B3s[tid - 64] = b3[tid - 64];
    }
    // per-pair quadratic weights around nearest node k (nodes k-1,k,k+1)
    #pragma unroll
    for (int p = tid; p < 1024; p += 512) {
        const int i = p >> 4, jj = p & 15;
        float d = dist[(m * 64 + i) * 64 + j0 + jj];
        float t = d * INV_H;
        int k = __float2int_rn(t);
        k = min(max(k, 1), S_INT - 1);
        float u = t - (float)k;
        float wm = 0.5f * u * (u - 1.0f);
        float w0 = 1.0f - u * u;
        float wp = 0.5f * u * (u + 1.0f);
        float4 wk;
        wk.x = __uint_as_float(h2bits(wm));
        wk.y = __uint_as_float(h2bits(w0));
        wk.z = __uint_as_float(h2bits(wp));
        wk.w = __int_as_float((k - 1) << 7);   // byte offset of first tap row
        ((float4*)W4s)[p] = wk;
    }
    __syncthreads();

    const int jj = tid >> 5;     // warp = destination atom
    const int t  = tid & 31;     // lane = channel pair (2t, 2t+1)

    u64 acc = 0ull;
    const char* tb = (const char*)TABu + (t << 2);
    const u64* V1v = (const u64*)V1s;
    const float4* W4v = ((const float4*)W4s) + jj;

    #pragma unroll 4
    for (int i = 0; i < 64; i++) {
        float4 wk = W4v[i << 4];                     // broadcast
        int koff = __float_as_int(wk.w);
        unsigned r0 = *(const unsigned*)(tb + koff);
        unsigned r1 = *(const unsigned*)(tb + koff + 128);
        unsigned r2 = *(const unsigned*)(tb + koff + 256);
        __half2 h2 = __hfma2(bits2h(__float_as_uint(wk.x)), bits2h(r0),
                     __hfma2(bits2h(__float_as_uint(wk.y)), bits2h(r1),
                     __hmul2(bits2h(__float_as_uint(wk.z)), bits2h(r2))));
        float2 hf = __half22float2(h2);
        u64 vv = V1v[(i << 5) + t];
        acc = fma2(vv, pack2(hf.x, hf.y), acc);
    }
    ((u64*)PAIRs)[(jj << 5) + t] = acc;
    __syncthreads();

    // stage W2T/W3T into dead table region
    float* W2Ts = (float*)TABu;
    float* W3Ts = W2Ts + 4096;
    {
        const float4* w2s = (const float4*)g_W2t;
        const float4* w3s = (const float4*)g_W3t;
        ((float4*)W2Ts)[tid]       = w2s[tid];
        ((float4*)W2Ts)[tid + 512] = w2s[tid + 512];
        ((float4*)W3Ts)[tid]       = w3s[tid];
        ((float4*)W3Ts)[tid + 512] = w3s[tid + 512];
    }
    __syncthreads();

    // epilogue: 8 warps, each handles 2 j-rows; lane = output pair (2t,2t+1)
    if (tid < 256) {
        const int g  = tid >> 5;      // 0..7
        const int jj0 = g, jj1 = g + 8;

        // layer 2: v2 = softplus(PAIR @ W2^T + b2)
        u64 a0, a1;
        {
            u64 bp = ((const u64*)B2s)[t];
            a0 = bp; a1 = bp;
            const float4* pr0 = (const float4*)(PAIRs + jj0 * 64);
            const float4* pr1 = (const float4*)(PAIRs + jj1 * 64);
            const u64* wv = (const u64*)W2Ts;
            #pragma unroll 4
            for (int c4 = 0; c4 < 16; c4++) {
                float4 p0 = pr0[c4];
                float4 p1 = pr1[c4];
                u64 w0 = wv[(c4 * 4 + 0) * 32 + t];
                u64 w1 = wv[(c4 * 4 + 1) * 32 + t];
                u64 w2 = wv[(c4 * 4 + 2) * 32 + t];
                u64 w3 = wv[(c4 * 4 + 3) * 32 + t];
                a0 = fma2(dup2(p0.x), w0, a0); a1 = fma2(dup2(p1.x), w0, a1);
                a0 = fma2(dup2(p0.y), w1, a0); a1 = fma2(dup2(p1.y), w1, a1);
                a0 = fma2(dup2(p0.z), w2, a0); a1 = fma2(dup2(p1.z), w2, a1);
                a0 = fma2(dup2(p0.w), w3, a0); a1 = fma2(dup2(p1.w), w3, a1);
            }
            float2 f0 = unpk2(a0), f1 = unpk2(a1);
            ((u64*)V2s)[jj0 * 32 + t] = pack2(softplus_f(f0.x), softplus_f(f0.y));
            ((u64*)V2s)[jj1 * 32 + t] = pack2(softplus_f(f1.x), softplus_f(f1.y));
        }
        __syncwarp();

        // layer 3 + residual
        {
            u64 bp = ((const u64*)B3s)[t];
            a0 = bp; a1 = bp;
            const float4* pr0 = (const float4*)(V2s + jj0 * 64);
            const float4* pr1 = (const float4*)(V2s + jj1 * 64);
            const u64* wv = (const u64*)W3Ts;
            #pragma unroll 4
            for (int c4 = 0; c4 < 16; c4++) {
                float4 p0 = pr0[c4];
                float4 p1 = pr1[c4];
                u64 w0 = wv[(c4 * 4 + 0) * 32 + t];
                u64 w1 = wv[(c4 * 4 + 1) * 32 + t];
                u64 w2 = wv[(c4 * 4 + 2) * 32 + t];
                u64 w3 = wv[(c4 * 4 + 3) * 32 + t];
                a0 = fma2(dup2(p0.x), w0, a0); a1 = fma2(dup2(p1.x), w0, a1);
                a0 = fma2(dup2(p0.y), w1, a0); a1 = fma2(dup2(p1.y), w1, a1);
                a0 = fma2(dup2(p0.z), w2, a0); a1 = fma2(dup2(p1.z), w2, a1);
                a0 = fma2(dup2(p0.w), w3, a0); a1 = fma2(dup2(p1.w), w3, a1);
            }
            const u64* xv = (const u64*)x;
            u64* ov = (u64*)out;
            int g0 = (m * 64 + j0 + jj0) * 32 + t;
            int g1 = (m * 64 + j0 + jj1) * 32 + t;
            float2 f0 = unpk2(a0), x0 = unpk2(xv[g0]);
            float2 f1 = unpk2(a1), x1 = unpk2(xv[g1]);
            ov[g0] = pack2(f0.x + x0.x, f0.y + x0.y);
            ov[g1] = pack2(f1.x + x1.x, f1.y + x1.y);
        }
    }
}

extern "C" void kernel_launch(void* const* d_in, const int* in_sizes, int n_in,
                              void* d_out, int out_size) {
    const float* x   = (const float*)d_in[0];
    const float* dist= (const float*)d_in[1];
    const float* W1  = (const float*)d_in[2];
    const float* b1  = (const float*)d_in[3];
    const float* W2  = (const float*)d_in[4];
    const float* b2  = (const float*)d_in[5];
    const float* W3  = (const float*)d_in[6];
    const float* b3  = (const float*)d_in[7];
    const float* Wd1 = (const float*)d_in[8];
    const float* bd1 = (const float*)d_in[9];
    const float* Wd2 = (const float*)d_in[10];
    const float* bd2 = (const float*)d_in[11];
    float* out = (float*)d_out;
    (void)in_sizes; (void)n_in; (void)out_size;

    cudaFuncSetAttribute(prep_kernel, cudaFuncAttributeMaxDynamicSharedMemorySize, PREP_SMEM);
    cudaFuncSetAttribute(main_kernel, cudaFuncAttributeMaxDynamicSharedMemorySize, MAIN_SMEM);

    prep_kernel<<<PREP_BLOCKS, 512, PREP_SMEM>>>(x, W1, b1, W2, W3, Wd1, bd1, Wd2, bd2);
    main_kernel<<<128, 512, MAIN_SMEM>>>(x, dist, b2, b3, out);
}

// round 5
// speedup vs baseline: 1.3028x; 1.0915x over previous
#include <cuda_runtime.h>
#include <cuda_fp16.h>
#include <math.h>

#define HIDDEN 64
#define MBATCH 32
#define ATOM   64
#define NUM_RBF 300

#define S_INT   512
#define TAB_ROWS 513                    // row s = h(s*H_STEP), s in [0,512]
#define H_STEP  (10.0f / 512.0f)
#define INV_H   51.2f

typedef unsigned long long u64;

// device scratch (no allocations allowed)
__device__ __align__(16) unsigned g_table_h[515 * 32];   // fp16x2 table, row=128B
__device__ __align__(16) float g_v1[MBATCH * ATOM * HIDDEN];
__device__ __align__(16) float g_W2t[HIDDEN * HIDDEN];
__device__ __align__(16) float g_W3t[HIDDEN * HIDDEN];

__device__ __forceinline__ float softplus_f(float v) {
    return fmaxf(v, 0.0f) + log1pf(expf(-fabsf(v)));
}

// packed f32x2 helpers (Blackwell FFMA2 / FADD2)
__device__ __forceinline__ u64 fma2(u64 a, u64 b, u64 c) {
    u64 d; asm("fma.rn.f32x2 %0, %1, %2, %3;" : "=l"(d) : "l"(a), "l"(b), "l"(c)); return d;
}
__device__ __forceinline__ u64 add2(u64 a, u64 b) {
    u64 d; asm("add.rn.f32x2 %0, %1, %2;" : "=l"(d) : "l"(a), "l"(b)); return d;
}
__device__ __forceinline__ u64 pack2(float a, float b) {
    u64 d; asm("mov.b64 %0, {%1, %2};" : "=l"(d) : "f"(a), "f"(b)); return d;
}
__device__ __forceinline__ float2 unpk2(u64 v) {
    float2 f; asm("mov.b64 {%0, %1}, %2;" : "=f"(f.x), "=f"(f.y) : "l"(v)); return f;
}
__device__ __forceinline__ u64 dup2(float v) {
    u64 d; asm("mov.b64 %0, {%1, %1};" : "=l"(d) : "f"(v)); return d;
}
__device__ __forceinline__ unsigned h2bits(float w) {
    __half2 h = __float2half2_rn(w);
    return *reinterpret_cast<unsigned*>(&h);
}
__device__ __forceinline__ __half2 bits2h(unsigned u) {
    return *reinterpret_cast<__half2*>(&u);
}

// ---------------------------------------------------------------------------
// Prep kernel (unchanged from R4), 512 threads/block
// ---------------------------------------------------------------------------
#define TAB_BLOCKS 65
#define V1_BLOCKS  64
#define PREP_BLOCKS (TAB_BLOCKS + V1_BLOCKS + 1)
#define PREP_SMEM ((64*301 + 64*65 + 8*304 + 8*64) * 4)

__global__ void __launch_bounds__(512) prep_kernel(
    const float* __restrict__ x,  const float* __restrict__ W1, const float* __restrict__ b1,
    const float* __restrict__ W2, const float* __restrict__ W3,
    const float* __restrict__ Wd1, const float* __restrict__ bd1,
    const float* __restrict__ Wd2, const float* __restrict__ bd2)
{
    extern __shared__ float sh[];
    const int tid = threadIdx.x;
    const int b = blockIdx.x;

    if (b < TAB_BLOCKS) {
        float* Wd1_s = sh;                   // 64 x 301 (padded)
        float* Wd2_s = Wd1_s + 64 * 301;     // 64 x 65
        float* rbf_s = Wd2_s + 64 * 65;      // 8 x 304
        float* g_s   = rbf_s + 8 * 304;      // 8 x 64

        for (int idx = tid; idx < 64 * NUM_RBF; idx += 512) {
            int cc = idx / NUM_RBF;
            int r  = idx - cc * NUM_RBF;
            Wd1_s[cc * 301 + r] = Wd1[idx];
        }
        for (int idx = tid; idx < 4096; idx += 512)
            Wd2_s[(idx >> 6) * 65 + (idx & 63)] = Wd2[idx];
        const int s0 = b * 8;
        for (int idx = tid; idx < 8 * NUM_RBF; idx += 512) {
            int qq = idx / NUM_RBF;
            int r  = idx - qq * NUM_RBF;
            float dd = (float)(s0 + qq) * H_STEP;
            float u = dd - 0.1f * (float)r;
            rbf_s[qq * 304 + r] = __expf(-10.0f * u * u);
        }
        __syncthreads();

        const int q = tid >> 6;
        const int c = tid & 63;
        const int s = s0 + q;
        const float d = (float)s * H_STEP;
        int rlo = (int)ceilf((d - 1.5f) * 10.0f); if (rlo < 0) rlo = 0;
        int rhi = (int)floorf((d + 1.5f) * 10.0f); if (rhi > NUM_RBF - 1) rhi = NUM_RBF - 1;
        float p = bd1[c];
        const float* wrow = Wd1_s + c * 301;
        const float* rrow = rbf_s + q * 304;
        for (int r = rlo; r <= rhi; r++) p = fmaf(wrow[r], rrow[r], p);
        g_s[q * 64 + c] = softplus_f(p);
        __syncthreads();

        float qv = bd2[c];
        const float* w2row = Wd2_s + c * 65;
        const float* gg = g_s + q * 64;
        #pragma unroll 8
        for (int k = 0; k < 64; k++) qv = fmaf(w2row[k], gg[k], qv);
        if (s < TAB_ROWS)
            ((__half*)g_table_h)[s * 64 + c] = __float2half_rn(softplus_f(qv));
    } else if (b < TAB_BLOCKS + V1_BLOCKS) {
        const int v = b - TAB_BLOCKS;
        const int m = v >> 1, half = v & 1;
        float* W1p = sh;                 // 64 x 68 padded
        float* xp  = sh + 64 * 68;       // 32 x 68

        for (int idx = tid; idx < 4096; idx += 512)
            W1p[(idx >> 6) * 68 + (idx & 63)] = W1[idx];
        for (int idx = tid; idx < 2048; idx += 512)
            xp[(idx >> 6) * 68 + (idx & 63)] = x[m * 4096 + (half * 32 + (idx >> 6)) * 64 + (idx & 63)];
        __syncthreads();

        const int ii = tid & 31;
        const int oh = tid >> 5;
        float4 acc = make_float4(0.f, 0.f, 0.f, 0.f);
        const float* xr = xp + ii * 68;
        const float* wr = W1p + oh * 4 * 68;
        #pragma unroll
        for (int c4 = 0; c4 < 16; c4++) {
            float4 xv = *(const float4*)(xr + c4 * 4);
            float4 w0 = *(const float4*)(wr + 0 * 68 + c4 * 4);
            float4 w1 = *(const float4*)(wr + 1 * 68 + c4 * 4);
            float4 w2 = *(const float4*)(wr + 2 * 68 + c4 * 4);
            float4 w3 = *(const float4*)(wr + 3 * 68 + c4 * 4);
            acc.x = fmaf(xv.x, w0.x, fmaf(xv.y, w0.y, fmaf(xv.z, w0.z, fmaf(xv.w, w0.w, acc.x))));
            acc.y = fmaf(xv.x, w1.x, fmaf(xv.y, w1.y, fmaf(xv.z, w1.z, fmaf(xv.w, w1.w, acc.y))));
            acc.z = fmaf(xv.x, w2.x, fmaf(xv.y, w2.y, fmaf(xv.z, w2.z, fmaf(xv.w, w2.w, acc.z))));
            acc.w = fmaf(xv.x, w3.x, fmaf(xv.y, w3.y, fmaf(xv.z, w3.z, fmaf(xv.w, w3.w, acc.w))));
        }
        float4 bv = *(const float4*)(b1 + oh * 4);
        acc.x += bv.x; acc.y += bv.y; acc.z += bv.z; acc.w += bv.w;
        *(float4*)(g_v1 + (m * 64 + half * 32 + ii) * 64 + oh * 4) = acc;
    } else {
        for (int idx = tid; idx < 8192; idx += 512) {
            const float* src = (idx < 4096) ? W2 : W3;
            float* dst = (idx < 4096) ? g_W2t : g_W3t;
            int e = idx & 4095;
            dst[e] = src[(e & 63) * 64 + (e >> 6)];
        }
    }
}

// ---------------------------------------------------------------------------
// Main kernel: 128 blocks = (m, j-group of 16), 1024 threads (32 warps).
// Warp = (ihalf, jj); lane = channel pair (2t, 2t+1). Each warp does 32
// i-iterations; 2-way partials reduced with FADD2. Quadratic 3-tap fp16
// interpolation, conflict-free smem layout.
// ---------------------------------------------------------------------------
// smem units: TAB 16480 | V1 4096 | W4 4096 | PART 2048 | PAIR 1024 |
// V2 1024 | B2 64 | B3 64  = 28896 floats = 115584 B  -> 1 CTA/SM
#define MAIN_SMEM (28896 * 4)

__global__ void __launch_bounds__(1024) main_kernel(
    const float* __restrict__ x, const float* __restrict__ dist,
    const float* __restrict__ b2, const float* __restrict__ b3,
    float* __restrict__ out)
{
    extern __shared__ float sh[];
    unsigned* TABu = (unsigned*)sh;       // fp16 table; reused as W2T/W3T later
    float* V1s  = sh + 16480;             // 4096
    float* W4s  = V1s + 4096;             // 4096 : per-pair (wm,w0,wp h2-bits, koff)
    float* PARTs= W4s + 4096;             // 2048 : 2-way u64 partials
    float* PAIRs= PARTs + 2048;           // 1024
    float* V2s  = PAIRs + 1024;           // 1024
    float* B2s  = V2s + 1024;             // 64
    float* B3s  = B2s + 64;               // 64

    const int tid = threadIdx.x;
    const int m  = blockIdx.x >> 2;
    const int j0 = (blockIdx.x & 3) << 4;

    // stage table (fp16, 64.4KB) + v1 + biases
    {
        const uint4* ts = (const uint4*)g_table_h;
        uint4* td = (uint4*)TABu;
        for (int idx = tid; idx < 4120; idx += 1024) td[idx] = ts[idx];
        ((float4*)V1s)[tid] = ((const float4*)(g_v1 + m * 4096))[tid];
        if (tid < 64) B2s[tid] = b2[tid];
        else if (tid < 128) B3s[tid - 64] = b3[tid - 64];
    }
    // per-pair quadratic weights around nearest node k (nodes k-1,k,k+1)
    {
        const int p = tid;
        const int i = p >> 4, jj = p & 15;
        float d = dist[(m * 64 + i) * 64 + j0 + jj];
        float t = d * INV_H;
        int k = __float2int_rn(t);
        k = min(max(k, 1), S_INT - 1);
        float u = t - (float)k;
        float wm = 0.5f * u * (u - 1.0f);
        float w0 = 1.0f - u * u;
        float wp = 0.5f * u * (u + 1.0f);
        float4 wk;
        wk.x = __uint_as_float(h2bits(wm));
        wk.y = __uint_as_float(h2bits(w0));
        wk.z = __uint_as_float(h2bits(wp));
        wk.w = __int_as_float((k - 1) << 7);   // byte offset of first tap row
        ((float4*)W4s)[p] = wk;
    }
    __syncthreads();

    const int warp  = tid >> 5;
    const int jj    = warp & 15;     // destination atom
    const int ihalf = warp >> 4;     // 0..1 : i-range half
    const int t     = tid & 31;      // lane = channel pair (2t, 2t+1)

    u64 acc = 0ull;
    const char* tb = (const char*)TABu + (t << 2);
    const u64* V1v = (const u64*)V1s;
    const float4* W4v = ((const float4*)W4s) + jj;
    const int ibase = ihalf << 5;

    #pragma unroll 4
    for (int ii = 0; ii < 32; ii++) {
        const int i = ibase + ii;
        float4 wk = W4v[i << 4];                     // broadcast
        int koff = __float_as_int(wk.w);
        unsigned r0 = *(const unsigned*)(tb + koff);
        unsigned r1 = *(const unsigned*)(tb + koff + 128);
        unsigned r2 = *(const unsigned*)(tb + koff + 256);
        __half2 h2 = __hfma2(bits2h(__float_as_uint(wk.x)), bits2h(r0),
                     __hfma2(bits2h(__float_as_uint(wk.y)), bits2h(r1),
                     __hmul2(bits2h(__float_as_uint(wk.z)), bits2h(r2))));
        float2 hf = __half22float2(h2);
        u64 vv = V1v[(i << 5) + t];
        acc = fma2(vv, pack2(hf.x, hf.y), acc);
    }
    ((u64*)PARTs)[(ihalf << 9) + (jj << 5) + t] = acc;
    __syncthreads();

    // reduce 2-way partials (f32x2 add); stage W2T/W3T into dead table region
    if (tid < 512) {
        u64 a = add2(((const u64*)PARTs)[tid], ((const u64*)PARTs)[tid + 512]);
        ((u64*)PAIRs)[tid] = a;
    }
    float* W2Ts = (float*)TABu;
    float* W3Ts = W2Ts + 4096;
    {
        const float4* w2s = (const float4*)g_W2t;
        const float4* w3s = (const float4*)g_W3t;
        if (tid < 1024) {
            ((float4*)W2Ts)[tid] = w2s[tid];
            ((float4*)W3Ts)[tid] = w3s[tid];
        }
    }
    __syncthreads();

    // epilogue: 8 warps, each handles 2 j-rows; lane = output pair (2t,2t+1)
    if (tid < 256) {
        const int g  = tid >> 5;      // 0..7
        const int jj0 = g, jj1 = g + 8;

        // layer 2: v2 = softplus(PAIR @ W2^T + b2)
        u64 a0, a1;
        {
            u64 bp = ((const u64*)B2s)[t];
            a0 = bp; a1 = bp;
            const float4* pr0 = (const float4*)(PAIRs + jj0 * 64);
            const float4* pr1 = (const float4*)(PAIRs + jj1 * 64);
            const u64* wv = (const u64*)W2Ts;
            #pragma unroll 4
            for (int c4 = 0; c4 < 16; c4++) {
                float4 p0 = pr0[c4];
                float4 p1 = pr1[c4];
                u64 w0 = wv[(c4 * 4 + 0) * 32 + t];
                u64 w1 = wv[(c4 * 4 + 1) * 32 + t];
                u64 w2 = wv[(c4 * 4 + 2) * 32 + t];
                u64 w3 = wv[(c4 * 4 + 3) * 32 + t];
                a0 = fma2(dup2(p0.x), w0, a0); a1 = fma2(dup2(p1.x), w0, a1);
                a0 = fma2(dup2(p0.y), w1, a0); a1 = fma2(dup2(p1.y), w1, a1);
                a0 = fma2(dup2(p0.z), w2, a0); a1 = fma2(dup2(p1.z), w2, a1);
                a0 = fma2(dup2(p0.w), w3, a0); a1 = fma2(dup2(p1.w), w3, a1);
            }
            float2 f0 = unpk2(a0), f1 = unpk2(a1);
            ((u64*)V2s)[jj0 * 32 + t] = pack2(softplus_f(f0.x), softplus_f(f0.y));
            ((u64*)V2s)[jj1 * 32 + t] = pack2(softplus_f(f1.x), softplus_f(f1.y));
        }
        __syncwarp();

        // layer 3 + residual
        {
            u64 bp = ((const u64*)B3s)[t];
            a0 = bp; a1 = bp;
            const float4* pr0 = (const float4*)(V2s + jj0 * 64);
            const float4* pr1 = (const float4*)(V2s + jj1 * 64);
            const u64* wv = (const u64*)W3Ts;
            #pragma unroll 4
            for (int c4 = 0; c4 < 16; c4++) {
                float4 p0 = pr0[c4];
                float4 p1 = pr1[c4];
                u64 w0 = wv[(c4 * 4 + 0) * 32 + t];
                u64 w1 = wv[(c4 * 4 + 1) * 32 + t];
                u64 w2 = wv[(c4 * 4 + 2) * 32 + t];
                u64 w3 = wv[(c4 * 4 + 3) * 32 + t];
                a0 = fma2(dup2(p0.x), w0, a0); a1 = fma2(dup2(p1.x), w0, a1);
                a0 = fma2(dup2(p0.y), w1, a0); a1 = fma2(dup2(p1.y), w1, a1);
                a0 = fma2(dup2(p0.z), w2, a0); a1 = fma2(dup2(p1.z), w2, a1);
                a0 = fma2(dup2(p0.w), w3, a0); a1 = fma2(dup2(p1.w), w3, a1);
            }
            const u64* xv = (const u64*)x;
            u64* ov = (u64*)out;
            int g0 = (m * 64 + j0 + jj0) * 32 + t;
            int g1 = (m * 64 + j0 + jj1) * 32 + t;
            float2 f0 = unpk2(a0), x0 = unpk2(xv[g0]);
            float2 f1 = unpk2(a1), x1 = unpk2(xv[g1]);
            ov[g0] = pack2(f0.x + x0.x, f0.y + x0.y);
            ov[g1] = pack2(f1.x + x1.x, f1.y + x1.y);
        }
    }
}

extern "C" void kernel_launch(void* const* d_in, const int* in_sizes, int n_in,
                              void* d_out, int out_size) {
    const float* x   = (const float*)d_in[0];
    const float* dist= (const float*)d_in[1];
    const float* W1  = (const float*)d_in[2];
    const float* b1  = (const float*)d_in[3];
    const float* W2  = (const float*)d_in[4];
    const float* b2  = (const float*)d_in[5];
    const float* W3  = (const float*)d_in[6];
    const float* b3  = (const float*)d_in[7];
    const float* Wd1 = (const float*)d_in[8];
    const float* bd1 = (const float*)d_in[9];
    const float* Wd2 = (const float*)d_in[10];
    const float* bd2 = (const float*)d_in[11];
    float* out = (float*)d_out;
    (void)in_sizes; (void)n_in; (void)out_size;

    cudaFuncSetAttribute(prep_kernel, cudaFuncAttributeMaxDynamicSharedMemorySize, PREP_SMEM);
    cudaFuncSetAttribute(main_kernel, cudaFuncAttributeMaxDynamicSharedMemorySize, MAIN_SMEM);

    prep_kernel<<<PREP_BLOCKS, 512, PREP_SMEM>>>(x, W1, b1, W2, W3, Wd1, bd1, Wd2, bd2);
    main_kernel<<<128, 1024, MAIN_SMEM>>>(x, dist, b2, b3, out);
}